// round 1
// baseline (speedup 1.0000x reference)
#include <cuda_runtime.h>
#include <math.h>

// ---------------- problem constants ----------------
#define Bc     16
#define HDIM   224
#define CC     96
#define LL     (HDIM*HDIM)          // 50176
#define NTOK   (Bc*LL)              // 802816  (== #window tokens, no padding)
#define WSZ    7
#define NN     49
#define NWIN   32                   // windows per spatial dim
#define BW     (Bc*NWIN*NWIN)       // 16384 windows
#define NHH    3
#define HD     32
#define MLPH   384
#define SHIFTV 3
#define SCALEV 0.17677669529663687f // 32^-0.5

static const long long YE = (long long)NTOK * CC;              // 77,070,336
static const long long AE = (long long)BW * NHH * NN * NN;     // 118,013,952

// ---------------- scratch (device globals; no allocation allowed) ----------------
__device__ float g_hw [(long long)NTOK * CC];     // LN1 (window order) / LN2 output
__device__ float g_qkv[(long long)NTOK * 288];
__device__ float g_att[(long long)NTOK * CC];     // attention output (window order)
__device__ float g_hid[(long long)NTOK * MLPH];

// ---------------- helpers ----------------
__device__ __forceinline__ int winrow_to_token(int row) {
    // row = ((b*32 + wi)*32 + wj)*49 + n  ->  original token index (with shift roll)
    int n  = row % NN;  int w = row / NN;
    int wj = w % NWIN;  int t = w / NWIN;
    int wi = t % NWIN;  int bb = t / NWIN;
    int i = n / WSZ, j = n % WSZ;
    int r = wi*WSZ + i + SHIFTV; if (r >= HDIM) r -= HDIM;
    int c = wj*WSZ + j + SHIFTV; if (c >= HDIM) c -= HDIM;
    return bb*LL + r*HDIM + c;
}

// ---------------- LN (one warp per token; optional window gather) ----------------
template<bool GATHER>
__global__ void ln_kernel(const float* __restrict__ x, const float* __restrict__ g,
                          const float* __restrict__ b, float* __restrict__ out) {
    int gw   = (blockIdx.x * blockDim.x + threadIdx.x) >> 5;
    int lane = threadIdx.x & 31;
    if (gw >= NTOK) return;
    int src = GATHER ? winrow_to_token(gw) : gw;
    const float* xp = x + (long long)src * CC;
    float v0 = xp[lane], v1 = xp[lane+32], v2 = xp[lane+64];
    float s = v0 + v1 + v2;
    #pragma unroll
    for (int o = 16; o; o >>= 1) s += __shfl_xor_sync(0xffffffffu, s, o);
    float mu = s * (1.f/96.f);
    float d0 = v0-mu, d1 = v1-mu, d2 = v2-mu;
    float vs = d0*d0 + d1*d1 + d2*d2;
    #pragma unroll
    for (int o = 16; o; o >>= 1) vs += __shfl_xor_sync(0xffffffffu, vs, o);
    float rstd = rsqrtf(vs * (1.f/96.f) + 1e-5f);
    float* op = out + (long long)gw * CC;
    op[lane]    = d0*rstd*g[lane]    + b[lane];
    op[lane+32] = d1*rstd*g[lane+32] + b[lane+32];
    op[lane+64] = d2*rstd*g[lane+64] + b[lane+64];
}

// ---------------- generic small-N GEMM: C[M,N] = A[M,K] @ W[K,N] + bias ----------------
// Whole W resident in SMEM, persistent CTAs. epi: 0=store, 1=GELU(exact),
// 2=window-reverse scatter + residual(x), 3=in-place residual add.
template<int K, int N, int TT, int RT, int RN, int NTH>
__global__ void __launch_bounds__(NTH)
gemm_kernel(const float* __restrict__ A, const float* __restrict__ W,
            const float* __restrict__ bias, float* __restrict__ C,
            const float* __restrict__ resid, int epi, int numTiles) {
    extern __shared__ float sm[];
    float* sW = sm;            // K*N
    float* sA = sm + K*N;      // TT*K
    const int tid = threadIdx.x;
    const int NG  = N / RN;
    const int tg  = tid / NG;
    const int ng  = tid % NG;

    for (int idx = tid; idx < K*N; idx += NTH) sW[idx] = W[idx];
    __syncthreads();

    for (int tile = blockIdx.x; tile < numTiles; tile += gridDim.x) {
        __syncthreads();
        const float* Ap = A + (long long)tile * TT * K;
        for (int idx = tid; idx < TT*K; idx += NTH) sA[idx] = Ap[idx];
        __syncthreads();

        float acc[RT][RN];
        #pragma unroll
        for (int t = 0; t < RT; t++)
            #pragma unroll
            for (int r = 0; r < RN; r++) acc[t][r] = 0.f;

        #pragma unroll 4
        for (int k = 0; k < K; k++) {
            float a[RT], w[RN];
            #pragma unroll
            for (int t = 0; t < RT; t++) a[t] = sA[(tg*RT + t)*K + k];
            #pragma unroll
            for (int r = 0; r < RN; r++) w[r] = sW[k*N + ng*RN + r];
            #pragma unroll
            for (int t = 0; t < RT; t++)
                #pragma unroll
                for (int r = 0; r < RN; r++) acc[t][r] += a[t] * w[r];
        }

        #pragma unroll
        for (int t = 0; t < RT; t++) {
            int row = tile*TT + tg*RT + t;
            long long dst = (long long)row * N;
            if (epi == 2) dst = (long long)winrow_to_token(row) * N;
            #pragma unroll
            for (int r = 0; r < RN; r++) {
                int col = ng*RN + r;
                float val = acc[t][r] + bias[col];
                if (epi == 0) {
                    C[dst + col] = val;
                } else if (epi == 1) {
                    C[dst + col] = 0.5f * val * (1.f + erff(val * 0.70710678118654752f));
                } else if (epi == 2) {
                    C[dst + col] = resid[dst + col] + val;
                } else {
                    C[dst + col] = C[dst + col] + val;
                }
            }
        }
    }
}

// ---------------- window attention: one block per (window, head) ----------------
__global__ void __launch_bounds__(64)
attn_kernel(const float* __restrict__ qkv, const float* __restrict__ rpb,
            float* __restrict__ attn_w, float* __restrict__ outp) {
    const int blk = blockIdx.x;
    const int h   = blk % NHH;
    const int w   = blk / NHH;
    __shared__ float sq[NN*HD], sk[NN*HD], sv[NN*HD];
    __shared__ float srpb[169];
    __shared__ float s_a[NN*53];           // stride 53: conflict-free
    const int tid = threadIdx.x;

    const float* base = qkv + (long long)w * NN * 288;
    for (int idx = tid; idx < NN*HD; idx += 64) {
        int n = idx >> 5, d = idx & 31;
        long long o = (long long)n*288 + h*HD + d;
        sq[idx] = base[o];
        sk[idx] = base[o + 96];
        sv[idx] = base[o + 192];
    }
    for (int idx = tid; idx < 169; idx += 64) srpb[idx] = rpb[idx*NHH + h];
    __syncthreads();

    if (tid < NN) {
        const int n = tid, i1 = n / WSZ, j1 = n % WSZ;
        float q[HD];
        #pragma unroll
        for (int d = 0; d < HD; d++) q[d] = sq[n*HD + d] * SCALEV;

        float mx = -1e30f;
        for (int m = 0; m < NN; m++) {
            float dot = 0.f;
            #pragma unroll
            for (int d = 0; d < HD; d++) dot += q[d] * sk[m*HD + d];
            int i2 = m / WSZ, j2 = m % WSZ;
            dot += srpb[(i1 - i2 + 6)*13 + (j1 - j2 + 6)];
            s_a[n*53 + m] = dot;
            mx = fmaxf(mx, dot);
        }
        float ssum = 0.f;
        for (int m = 0; m < NN; m++) {
            float e = __expf(s_a[n*53 + m] - mx);
            s_a[n*53 + m] = e;
            ssum += e;
        }
        float inv = 1.f / ssum;
        float* ap = attn_w ? attn_w + ((long long)(w*NHH + h)*NN + n)*NN : (float*)0;
        for (int m = 0; m < NN; m++) {
            float v = s_a[n*53 + m] * inv;
            s_a[n*53 + m] = v;
            if (ap) ap[m] = v;
        }
        float* op = outp + ((long long)w*NN + n)*CC + h*HD;
        #pragma unroll 4
        for (int d = 0; d < HD; d++) {
            float o = 0.f;
            for (int m = 0; m < NN; m++) o += s_a[n*53 + m] * sv[m*HD + d];
            op[d] = o;
        }
    }
}

// ---------------- launch ----------------
extern "C" void kernel_launch(void* const* d_in, const int* in_sizes, int n_in,
                              void* d_out, int out_size) {
    const float* x      = (const float*)d_in[0];
    const float* w_qkv  = (const float*)d_in[1];
    const float* b_qkv  = (const float*)d_in[2];
    const float* w_proj = (const float*)d_in[3];
    const float* b_proj = (const float*)d_in[4];
    const float* rpb    = (const float*)d_in[5];
    const float* gamma1 = (const float*)d_in[6];
    const float* beta1  = (const float*)d_in[7];
    const float* gamma2 = (const float*)d_in[8];
    const float* beta2  = (const float*)d_in[9];
    const float* w_fc1  = (const float*)d_in[10];
    const float* b_fc1  = (const float*)d_in[11];
    const float* w_fc2  = (const float*)d_in[12];
    const float* b_fc2  = (const float*)d_in[13];

    float* y = (float*)d_out;
    float* attn_w = ((long long)out_size >= YE + AE) ? (y + YE) : (float*)0;

    float *p_hw, *p_qkv, *p_att, *p_hid;
    cudaGetSymbolAddress((void**)&p_hw,  g_hw);
    cudaGetSymbolAddress((void**)&p_qkv, g_qkv);
    cudaGetSymbolAddress((void**)&p_att, g_att);
    cudaGetSymbolAddress((void**)&p_hid, g_hid);

    // dynamic smem budgets
    const int SM_QKV = (96*288 + 16*96) * 4;   // 116736
    const int SM_PRJ = (96*96  + 32*96) * 4;   //  49152
    const int SM_FC1 = (96*384 + 16*96) * 4;   // 153600
    const int SM_FC2 = (384*96 + 32*384) * 4;  // 196608
    cudaFuncSetAttribute((const void*)gemm_kernel<96,288,16,4,6,192>,
                         cudaFuncAttributeMaxDynamicSharedMemorySize, SM_QKV);
    cudaFuncSetAttribute((const void*)gemm_kernel<96, 96,32,4,4,192>,
                         cudaFuncAttributeMaxDynamicSharedMemorySize, SM_PRJ);
    cudaFuncSetAttribute((const void*)gemm_kernel<96,384,16,4,6,256>,
                         cudaFuncAttributeMaxDynamicSharedMemorySize, SM_FC1);
    cudaFuncSetAttribute((const void*)gemm_kernel<384,96,32,4,4,192>,
                         cudaFuncAttributeMaxDynamicSharedMemorySize, SM_FC2);

    // 1) LN1 + shifted-window gather (window token order)
    ln_kernel<true><<<NTOK/8, 256>>>(x, gamma1, beta1, p_hw);

    // 2) qkv = hw @ w_qkv + b
    gemm_kernel<96,288,16,4,6,192><<<148, 192, SM_QKV>>>(
        p_hw, w_qkv, b_qkv, p_qkv, (const float*)0, 0, NTOK/16);

    // 3) windowed attention (+ write attention weights)
    attn_kernel<<<BW*NHH, 64>>>(p_qkv, rpb, attn_w, p_att);

    // 4) proj + window-reverse scatter + residual -> y
    gemm_kernel<96,96,32,4,4,192><<<592, 192, SM_PRJ>>>(
        p_att, w_proj, b_proj, y, x, 2, NTOK/32);

    // 5) LN2
    ln_kernel<false><<<NTOK/8, 256>>>(y, gamma2, beta2, p_hw);

    // 6) fc1 + exact GELU
    gemm_kernel<96,384,16,4,6,256><<<148, 256, SM_FC1>>>(
        p_hw, w_fc1, b_fc1, p_hid, (const float*)0, 1, NTOK/16);

    // 7) fc2 + residual (in place on y)
    gemm_kernel<384,96,32,4,4,192><<<148, 192, SM_FC2>>>(
        p_hid, w_fc2, b_fc2, y, (const float*)0, 3, NTOK/32);
}

// round 3
// speedup vs baseline: 2.3086x; 2.3086x over previous
#include <cuda_runtime.h>
#include <cuda_bf16.h>
#include <mma.h>
#include <math.h>
#include <stdint.h>

using namespace nvcuda;
typedef __nv_bfloat16 bf16;

// ---------------- problem constants ----------------
#define Bc     16
#define HDIM   224
#define CC     96
#define LL     (HDIM*HDIM)
#define NTOK   (Bc*LL)              // 802816
#define WSZ    7
#define NN     49
#define NWIN   32
#define BW     (Bc*NWIN*NWIN)       // 16384
#define NHH    3
#define HD     32
#define MLPH   384
#define SHIFTV 3
#define SCALEV 0.17677669529663687f

static const long long YE = (long long)NTOK * CC;
static const long long AE = (long long)BW * NHH * NN * NN;

// ---------------- scratch ----------------
__device__ bf16 g_hw [(size_t)NTOK * CC];
__device__ bf16 g_qkv[(size_t)NTOK * 288];
__device__ bf16 g_att[(size_t)NTOK * CC];
__device__ bf16 g_hid[(size_t)NTOK * MLPH];

// ---------------- helpers ----------------
__device__ __forceinline__ int winrow_to_token(int row) {
    int n  = row % NN;  int w = row / NN;
    int wj = w % NWIN;  int t = w / NWIN;
    int wi = t % NWIN;  int bb = t / NWIN;
    int i = n / WSZ, j = n % WSZ;
    int r = wi*WSZ + i + SHIFTV; if (r >= HDIM) r -= HDIM;
    int c = wj*WSZ + j + SHIFTV; if (c >= HDIM) c -= HDIM;
    return bb*LL + r*HDIM + c;
}

// ---------------- LN -> bf16 (optional shifted-window gather) ----------------
template<bool GATHER>
__global__ void ln_kernel(const float* __restrict__ x, const float* __restrict__ g,
                          const float* __restrict__ b, bf16* __restrict__ out) {
    int gw   = (blockIdx.x * blockDim.x + threadIdx.x) >> 5;
    int lane = threadIdx.x & 31;
    if (gw >= NTOK) return;
    int src = GATHER ? winrow_to_token(gw) : gw;
    const float* xp = x + (size_t)src * CC;
    float v0 = xp[lane], v1 = xp[lane+32], v2 = xp[lane+64];
    float s = v0 + v1 + v2;
    #pragma unroll
    for (int o = 16; o; o >>= 1) s += __shfl_xor_sync(0xffffffffu, s, o);
    float mu = s * (1.f/96.f);
    float d0 = v0-mu, d1 = v1-mu, d2 = v2-mu;
    float vs = d0*d0 + d1*d1 + d2*d2;
    #pragma unroll
    for (int o = 16; o; o >>= 1) vs += __shfl_xor_sync(0xffffffffu, vs, o);
    float rstd = rsqrtf(vs * (1.f/96.f) + 1e-5f);
    bf16* op = out + (size_t)gw * CC;
    op[lane]    = __float2bfloat16(d0*rstd*g[lane]    + b[lane]);
    op[lane+32] = __float2bfloat16(d1*rstd*g[lane+32] + b[lane+32]);
    op[lane+64] = __float2bfloat16(d2*rstd*g[lane+64] + b[lane+64]);
}

// ---------------- WMMA (HMMA) GEMM ----------------
// C[M,N] = A[M,K] @ W[K,N] (+bias, +epilogue).  A bf16 row-major, W f32 -> bf16 smem.
// M tile = 128 (8 warps x 16 rows), N processed in 96-wide chunks (6 frags/warp).
// EPI: 0 = bf16 store, 1 = GELU + bf16 store,
//      2 = window-reverse scatter + residual(x) -> f32, 3 = f32 += (in place).
template<int K, int NCH, int EPI, int NOUT>
__global__ void __launch_bounds__(256)
wmma_gemm(const bf16* __restrict__ A, const float* __restrict__ W,
          const float* __restrict__ bias, void* __restrict__ Cv,
          const float* __restrict__ resid, int numTiles)
{
    constexpr int N     = NCH * 96;
    constexpr int LDW   = N + 8;             // bf16 elements
    constexpr int LDA   = K + 8;             // bf16 elements
    constexpr int LDS   = 100;               // f32 staging ld
    constexpr int WBY   = K * LDW * 2;
    constexpr int ABY   = 128 * LDA * 2;
    constexpr bool ALIAS = (NCH == 1);
    constexpr int SBY   = 128 * LDS * 4;     // 51200
    constexpr int AREG  = ALIAS ? (ABY > SBY ? ABY : SBY) : ABY;

    extern __shared__ __align__(16) char smem[];
    bf16*  sW   = (bf16*)smem;
    bf16*  sA   = (bf16*)(smem + WBY);
    float* stag = ALIAS ? (float*)(smem + WBY) : (float*)(smem + WBY + ABY);
    int*   stok = (int*)(smem + WBY + AREG + (ALIAS ? 0 : SBY));

    const int tid  = threadIdx.x;
    const int warp = tid >> 5;

    // weights -> smem bf16
    for (int idx = tid; idx < K * N; idx += 256) {
        int k = idx / N, n = idx - k * N;
        sW[k * LDW + n] = __float2bfloat16(W[(size_t)k * N + n]);
    }
    __syncthreads();

    constexpr int CPR = K / 8;   // 16B chunks per A row

    for (int tile = blockIdx.x; tile < numTiles; tile += gridDim.x) {
        // ---- load A tile ----
        const uint4* Ag = (const uint4*)(A + (size_t)tile * 128 * K);
        #pragma unroll 4
        for (int idx = tid; idx < 128 * CPR; idx += 256) {
            int r = idx / CPR, cc = idx - r * CPR;
            *(uint4*)(sA + r * LDA + cc * 8) = Ag[(size_t)r * CPR + cc];
        }
        if (EPI == 2 && tid < 128) stok[tid] = winrow_to_token(tile * 128 + tid);
        __syncthreads();

        for (int c = 0; c < NCH; c++) {
            wmma::fragment<wmma::accumulator, 16, 16, 16, float> acc[6];
            #pragma unroll
            for (int f = 0; f < 6; f++) wmma::fill_fragment(acc[f], 0.f);

            #pragma unroll
            for (int ks = 0; ks < K / 16; ks++) {
                wmma::fragment<wmma::matrix_a, 16, 16, 16, bf16, wmma::row_major> af;
                wmma::load_matrix_sync(af, sA + (warp * 16) * LDA + ks * 16, LDA);
                #pragma unroll
                for (int f = 0; f < 6; f++) {
                    wmma::fragment<wmma::matrix_b, 16, 16, 16, bf16, wmma::row_major> bfr;
                    wmma::load_matrix_sync(bfr, sW + (ks * 16) * LDW + c * 96 + f * 16, LDW);
                    wmma::mma_sync(acc[f], af, bfr, acc[f]);
                }
            }
            __syncthreads();   // protect aliased A region / prev staging readers
            #pragma unroll
            for (int f = 0; f < 6; f++)
                wmma::store_matrix_sync(stag + (warp * 16) * LDS + f * 16, acc[f], LDS, wmma::mem_row_major);
            __syncthreads();

            // ---- epilogue: staging -> gmem ----
            for (int i = tid; i < 128 * 96; i += 256) {
                int r = i / 96, col0 = i - r * 96;
                int col = c * 96 + col0;
                float v = stag[r * LDS + col0] + __ldg(&bias[col]);
                int row = tile * 128 + r;
                if (EPI == 1) v = 0.5f * v * (1.f + erff(v * 0.70710678118654752f));
                if (EPI == 0 || EPI == 1) {
                    ((bf16*)Cv)[(size_t)row * NOUT + col] = __float2bfloat16(v);
                } else if (EPI == 2) {
                    int tok = stok[r];
                    ((float*)Cv)[(size_t)tok * 96 + col0] = resid[(size_t)tok * 96 + col0] + v;
                } else {
                    ((float*)Cv)[(size_t)row * 96 + col0] += v;
                }
            }
            __syncthreads();
        }
    }
}

// ---------------- window attention ----------------
__global__ void __launch_bounds__(64)
attn_kernel(const bf16* __restrict__ qkv, const float* __restrict__ rpb,
            float* __restrict__ attn_w, bf16* __restrict__ outp) {
    const int blk = blockIdx.x;
    const int h = blk % NHH, w = blk / NHH;
    __shared__ float sq[NN*HD], sk[NN*HD], sv[NN*HD];
    __shared__ float srpb[169];
    __shared__ float s_a[NN*53];
    const int tid = threadIdx.x;

    const bf16* base = qkv + (size_t)w * NN * 288 + h*HD;
    for (int idx = tid; idx < NN*12; idx += 64) {
        int n = idx / 12, p = idx - n*12;
        int which = p >> 2, ch = p & 3;
        uint4 vv = *(const uint4*)(base + (size_t)n*288 + which*96 + ch*8);
        const __nv_bfloat162* b2 = (const __nv_bfloat162*)&vv;
        float* dst = (which == 0 ? sq : which == 1 ? sk : sv) + n*HD + ch*8;
        #pragma unroll
        for (int t = 0; t < 4; t++) { float2 f = __bfloat1622float2(b2[t]); dst[2*t] = f.x; dst[2*t+1] = f.y; }
    }
    for (int idx = tid; idx < 169; idx += 64) srpb[idx] = rpb[idx*NHH + h];
    __syncthreads();

    if (tid < NN) {
        const int n = tid, i1 = n / WSZ, j1 = n % WSZ;
        float q[HD];
        #pragma unroll
        for (int d = 0; d < HD; d++) q[d] = sq[n*HD + d] * SCALEV;
        const float4* sk4 = (const float4*)sk;
        float mx = -1e30f;
        for (int m = 0; m < NN; m++) {
            float s0 = 0.f, s1 = 0.f, s2 = 0.f, s3 = 0.f;
            #pragma unroll
            for (int i = 0; i < 8; i++) {
                float4 kk = sk4[m*8 + i];
                s0 += q[4*i]*kk.x; s1 += q[4*i+1]*kk.y; s2 += q[4*i+2]*kk.z; s3 += q[4*i+3]*kk.w;
            }
            int i2 = m / WSZ, j2 = m % WSZ;
            float dot = (s0 + s1) + (s2 + s3) + srpb[(i1 - i2 + 6)*13 + (j1 - j2 + 6)];
            s_a[n*53 + m] = dot;
            mx = fmaxf(mx, dot);
        }
        float ss = 0.f;
        for (int m = 0; m < NN; m++) { float e = __expf(s_a[n*53 + m] - mx); s_a[n*53 + m] = e; ss += e; }
        float inv = 1.f / ss;
        for (int m = 0; m < NN; m++) s_a[n*53 + m] *= inv;
    }
    __syncthreads();

    if (attn_w) {
        float* ap = attn_w + (size_t)(w*NHH + h) * (NN*NN);
        for (int idx = tid; idx < NN*NN; idx += 64) ap[idx] = s_a[(idx/NN)*53 + idx % NN];
    }

    if (tid < NN) {
        const int n = tid;
        float4 o[8];
        #pragma unroll
        for (int i = 0; i < 8; i++) { o[i].x = 0.f; o[i].y = 0.f; o[i].z = 0.f; o[i].w = 0.f; }
        const float4* sv4 = (const float4*)sv;
        for (int m = 0; m < NN; m++) {
            float a = s_a[n*53 + m];
            #pragma unroll
            for (int i = 0; i < 8; i++) {
                float4 vv = sv4[m*8 + i];
                o[i].x += a*vv.x; o[i].y += a*vv.y; o[i].z += a*vv.z; o[i].w += a*vv.w;
            }
        }
        bf16* op = outp + (size_t)(w*NN + n) * CC + h*HD;
        uint32_t pk[16];
        #pragma unroll
        for (int i = 0; i < 8; i++) {
            __nv_bfloat162 p0 = __floats2bfloat162_rn(o[i].x, o[i].y);
            __nv_bfloat162 p1 = __floats2bfloat162_rn(o[i].z, o[i].w);
            pk[2*i]   = *(uint32_t*)&p0;
            pk[2*i+1] = *(uint32_t*)&p1;
        }
        #pragma unroll
        for (int t = 0; t < 4; t++) ((uint4*)op)[t] = ((const uint4*)pk)[t];
    }
}

// ---------------- launch ----------------
extern "C" void kernel_launch(void* const* d_in, const int* in_sizes, int n_in,
                              void* d_out, int out_size) {
    const float* x      = (const float*)d_in[0];
    const float* w_qkv  = (const float*)d_in[1];
    const float* b_qkv  = (const float*)d_in[2];
    const float* w_proj = (const float*)d_in[3];
    const float* b_proj = (const float*)d_in[4];
    const float* rpb    = (const float*)d_in[5];
    const float* gamma1 = (const float*)d_in[6];
    const float* beta1  = (const float*)d_in[7];
    const float* gamma2 = (const float*)d_in[8];
    const float* beta2  = (const float*)d_in[9];
    const float* w_fc1  = (const float*)d_in[10];
    const float* b_fc1  = (const float*)d_in[11];
    const float* w_fc2  = (const float*)d_in[12];
    const float* b_fc2  = (const float*)d_in[13];

    float* y = (float*)d_out;
    float* attn_w = ((long long)out_size >= YE + AE) ? (y + YE) : (float*)0;

    bf16 *p_hw, *p_qkv, *p_att, *p_hid;
    cudaGetSymbolAddress((void**)&p_hw,  g_hw);
    cudaGetSymbolAddress((void**)&p_qkv, g_qkv);
    cudaGetSymbolAddress((void**)&p_att, g_att);
    cudaGetSymbolAddress((void**)&p_hid, g_hid);

    // smem sizes (bytes): W + A (+staging if !alias, else max(A,staging)) + stok
    const int SM_QKV = 96*296*2  + 128*104*2 + 51200 + 512;  // 135168
    const int SM_PRJ = 96*104*2  + 51200 + 512;              //  71680 (alias)
    const int SM_FC1 = 96*392*2  + 128*104*2 + 51200 + 512;  // 153600
    const int SM_FC2 = 384*104*2 + 128*392*2 + 512;          // 180736 (alias, A>stag)

    cudaFuncSetAttribute(wmma_gemm<96, 3, 0, 288>, cudaFuncAttributeMaxDynamicSharedMemorySize, SM_QKV);
    cudaFuncSetAttribute(wmma_gemm<96, 1, 2,  96>, cudaFuncAttributeMaxDynamicSharedMemorySize, SM_PRJ);
    cudaFuncSetAttribute(wmma_gemm<96, 4, 1, 384>, cudaFuncAttributeMaxDynamicSharedMemorySize, SM_FC1);
    cudaFuncSetAttribute(wmma_gemm<384,1, 3,  96>, cudaFuncAttributeMaxDynamicSharedMemorySize, SM_FC2);

    const int numTiles = NTOK / 128;  // 6272

    // 1) LN1 + shifted-window gather -> bf16
    ln_kernel<true><<<NTOK/8, 256>>>(x, gamma1, beta1, p_hw);

    // 2) qkv GEMM (HMMA) -> bf16
    wmma_gemm<96, 3, 0, 288><<<148, 256, SM_QKV>>>(p_hw, w_qkv, b_qkv, (void*)p_qkv, (const float*)0, numTiles);

    // 3) window attention (+ attn weights)
    attn_kernel<<<BW*NHH, 64>>>(p_qkv, rpb, attn_w, p_att);

    // 4) proj GEMM + window-reverse scatter + residual -> y (f32)
    wmma_gemm<96, 1, 2, 96><<<296, 256, SM_PRJ>>>(p_att, w_proj, b_proj, (void*)y, x, numTiles);

    // 5) LN2 -> bf16
    ln_kernel<false><<<NTOK/8, 256>>>(y, gamma2, beta2, p_hw);

    // 6) fc1 + GELU -> bf16
    wmma_gemm<96, 4, 1, 384><<<148, 256, SM_FC1>>>(p_hw, w_fc1, b_fc1, (void*)p_hid, (const float*)0, numTiles);

    // 7) fc2 + residual (in place on y)
    wmma_gemm<384, 1, 3, 96><<<148, 256, SM_FC2>>>(p_hid, w_fc2, b_fc2, (void*)y, (const float*)0, numTiles);
}

// round 4
// speedup vs baseline: 3.2182x; 1.3940x over previous
#include <cuda_runtime.h>
#include <cuda_bf16.h>
#include <mma.h>
#include <math.h>
#include <stdint.h>

using namespace nvcuda;
typedef __nv_bfloat16 bf16;

// ---------------- problem constants ----------------
#define Bc     16
#define HDIM   224
#define CC     96
#define LL     (HDIM*HDIM)
#define NTOK   (Bc*LL)              // 802816
#define WSZ    7
#define NN     49
#define NWIN   32
#define BW     (Bc*NWIN*NWIN)       // 16384
#define NHH    3
#define HD     32
#define MLPH   384
#define SHIFTV 3
#define SCALEV 0.17677669529663687f
#define NUMTILES (NTOK/128)         // 6272
#define GRID   148

static const long long YE = (long long)NTOK * CC;
static const long long AE = (long long)BW * NHH * NN * NN;

// ---------------- scratch ----------------
__device__ bf16 g_hw [(size_t)NTOK * CC];
__device__ bf16 g_qkv[(size_t)NTOK * 288];
__device__ bf16 g_att[(size_t)NTOK * CC];
__device__ bf16 g_hid[(size_t)NTOK * MLPH];

// ---------------- helpers ----------------
__device__ __forceinline__ uint32_t smem_u32(const void* p) {
    uint32_t a;
    asm("{ .reg .u64 t; cvta.to.shared.u64 t, %1; cvt.u32.u64 %0, t; }" : "=r"(a) : "l"(p));
    return a;
}
__device__ __forceinline__ void cp16(void* d, const void* s) {
    asm volatile("cp.async.cg.shared.global [%0], [%1], 16;" :: "r"(smem_u32(d)), "l"(s));
}
#define CPC() asm volatile("cp.async.commit_group;" ::: "memory")
#define CPW() asm volatile("cp.async.wait_group 0;" ::: "memory")

__device__ __forceinline__ float wred(float v) {
    #pragma unroll
    for (int o = 16; o; o >>= 1) v += __shfl_xor_sync(0xffffffffu, v, o);
    return v;
}

__device__ __forceinline__ int winrow_to_token(int row) {
    int n  = row % NN;  int w = row / NN;
    int wj = w % NWIN;  int t = w / NWIN;
    int wi = t % NWIN;  int bb = t / NWIN;
    int i = n / WSZ, j = n % WSZ;
    int r = wi*WSZ + i + SHIFTV; if (r >= HDIM) r -= HDIM;
    int c = wj*WSZ + j + SHIFTV; if (c >= HDIM) c -= HDIM;
    return bb*LL + r*HDIM + c;
}

// =====================================================================
// qkv kernel: fused LN1 + shifted-window gather + GEMM (96 -> 288)
// =====================================================================
__global__ void __launch_bounds__(512, 1)
qkv_kernel(const float* __restrict__ x, const float* __restrict__ Wq,
           const float* __restrict__ bq, const float* __restrict__ g1,
           const float* __restrict__ b1, bf16* __restrict__ out)
{
    extern __shared__ __align__(16) char sm[];
    bf16*  sW   = (bf16*)sm;                       // 96*296       = 56832 B
    bf16*  sA   = (bf16*)(sm + 56832);             // 128*104      = 26624 B
    float* xst0 = (float*)(sm + 83456);            // 51200 B  (x rows f32 LDX=96 / epi stag LDS=100)
    float* xst1 = (float*)(sm + 83456 + 51200);    // 51200 B
    int*   stok = (int*)(sm + 185856);             // 2*128*4 = 1024 B
    float* sbias= (float*)(sm + 186880);           // 288*4 = 1152 B
    float* sg   = sbias + 288;                     // 96
    float* sb   = sg + 96;                         // 96  (total 188800)

    const int tid = threadIdx.x, warp = tid >> 5, lane = tid & 31;
    const int mw = warp >> 1, nw = warp & 1;

    for (int i = tid; i < 96*288; i += 512) { int k = i/288, n = i%288; sW[k*296+n] = __float2bfloat16(Wq[i]); }
    for (int i = tid; i < 288; i += 512) sbias[i] = bq[i];
    if (tid < 96) { sg[tid] = g1[tid]; sb[tid] = b1[tid]; }

    int tile = blockIdx.x, buf = 0;
    if (tid < 128) stok[tid] = winrow_to_token(tile*128 + tid);
    __syncthreads();
    for (int idx = tid; idx < 3072; idx += 512) {
        int r = idx/24, c = idx%24;
        cp16(xst0 + r*96 + c*4, x + (size_t)stok[r]*96 + c*4);
    }
    CPC();

    for (; tile < NUMTILES; tile += GRID) {
        CPW(); __syncthreads();
        float* xs = buf ? xst1 : xst0;

        // LN1: warp-per-row (16 warps x 8 rows)
        #pragma unroll
        for (int rr = 0; rr < 8; rr++) {
            int r = warp*8 + rr;
            float v0 = xs[r*96+lane], v1 = xs[r*96+lane+32], v2 = xs[r*96+lane+64];
            float mu = wred(v0+v1+v2) * (1.f/96.f);
            float d0 = v0-mu, d1 = v1-mu, d2 = v2-mu;
            float var = wred(d0*d0 + d1*d1 + d2*d2) * (1.f/96.f);
            float rs = rsqrtf(var + 1e-5f);
            sA[r*104+lane]    = __float2bfloat16(d0*rs*sg[lane]    + sb[lane]);
            sA[r*104+lane+32] = __float2bfloat16(d1*rs*sg[lane+32] + sb[lane+32]);
            sA[r*104+lane+64] = __float2bfloat16(d2*rs*sg[lane+64] + sb[lane+64]);
        }
        int nt = tile + GRID;
        int nb = buf ^ 1;
        if (tid < 128 && nt < NUMTILES) stok[nb*128 + tid] = winrow_to_token(nt*128 + tid);
        __syncthreads();
        if (nt < NUMTILES) {
            float* xn = nb ? xst1 : xst0;
            const int* st = stok + nb*128;
            for (int idx = tid; idx < 3072; idx += 512) {
                int r = idx/24, c = idx%24;
                cp16(xn + r*96 + c*4, x + (size_t)st[r]*96 + c*4);
            }
        }
        CPC();

        float* stag = xs;   // alias: x rows consumed, reuse as f32 staging (LDS=100)
        for (int c = 0; c < 3; c++) {
            wmma::fragment<wmma::accumulator, 16, 16, 16, float> acc[3];
            #pragma unroll
            for (int f = 0; f < 3; f++) wmma::fill_fragment(acc[f], 0.f);
            #pragma unroll
            for (int ks = 0; ks < 6; ks++) {
                wmma::fragment<wmma::matrix_a, 16, 16, 16, bf16, wmma::row_major> af;
                wmma::load_matrix_sync(af, sA + (mw*16)*104 + ks*16, 104);
                #pragma unroll
                for (int f = 0; f < 3; f++) {
                    wmma::fragment<wmma::matrix_b, 16, 16, 16, bf16, wmma::row_major> bfr;
                    wmma::load_matrix_sync(bfr, sW + (ks*16)*296 + c*96 + nw*48 + f*16, 296);
                    wmma::mma_sync(acc[f], af, bfr, acc[f]);
                }
            }
            __syncthreads();
            #pragma unroll
            for (int f = 0; f < 3; f++)
                wmma::store_matrix_sync(stag + (mw*16)*100 + nw*48 + f*16, acc[f], 100, wmma::mem_row_major);
            __syncthreads();
            #pragma unroll
            for (int i2 = tid; i2 < 128*48; i2 += 512) {
                int r = i2/48, p = i2 - r*48;
                float u0 = stag[r*100 + 2*p]     + sbias[c*96 + 2*p];
                float u1 = stag[r*100 + 2*p + 1] + sbias[c*96 + 2*p + 1];
                __nv_bfloat162 pk = __floats2bfloat162_rn(u0, u1);
                *(uint32_t*)(out + ((size_t)(tile*128 + r))*288 + c*96 + 2*p) = *(uint32_t*)&pk;
            }
            __syncthreads();
        }
        buf ^= 1;
    }
}

// =====================================================================
// proj kernel: GEMM (96 -> 96) + window-reverse scatter + residual + LN2
// writes y (f32, token order) and hw = LN2(y) (bf16, token order)
// =====================================================================
__global__ void __launch_bounds__(512, 1)
proj_kernel(const bf16* __restrict__ A, const float* __restrict__ Wp,
            const float* __restrict__ bp, const float* __restrict__ x,
            const float* __restrict__ g2, const float* __restrict__ b2,
            float* __restrict__ y, bf16* __restrict__ hw)
{
    extern __shared__ __align__(16) char sm[];
    bf16*  sW   = (bf16*)sm;                        // 96*104  = 19968
    bf16*  sA0  = (bf16*)(sm + 19968);              // 26624
    bf16*  sA1  = (bf16*)(sm + 46592);              // 26624
    float* stag = (float*)(sm + 73216);             // 128*100*4 = 51200
    float* rst0 = (float*)(sm + 124416);            // 128*96*4 = 49152
    float* rst1 = (float*)(sm + 173568);            // 49152
    int*   stok = (int*)(sm + 222720);              // 1024
    float* sbias= (float*)(sm + 223744);            // 384
    float* sg   = (float*)(sm + 224128);            // 384
    float* sb   = (float*)(sm + 224512);            // 384  (total 224896)

    const int tid = threadIdx.x, warp = tid >> 5, lane = tid & 31;
    const int mw = warp >> 1, nw = warp & 1;

    for (int i = tid; i < 96*96; i += 512) { int k = i/96, n = i%96; sW[k*104+n] = __float2bfloat16(Wp[i]); }
    if (tid < 96) { sbias[tid] = bp[tid]; sg[tid] = g2[tid]; sb[tid] = b2[tid]; }

    int tile = blockIdx.x, buf = 0;
    if (tid < 128) stok[tid] = winrow_to_token(tile*128 + tid);
    __syncthreads();
    {
        const bf16* Ag = A + (size_t)tile*128*96;
        for (int idx = tid; idx < 1536; idx += 512) { int r = idx/12, c = idx%12; cp16(sA0 + r*104 + c*8, Ag + r*96 + c*8); }
        for (int idx = tid; idx < 3072; idx += 512) { int r = idx/24, c = idx%24; cp16(rst0 + r*96 + c*4, x + (size_t)stok[r]*96 + c*4); }
    }
    CPC();

    for (; tile < NUMTILES; tile += GRID) {
        CPW(); __syncthreads();
        bf16*  sA  = buf ? sA1 : sA0;
        float* rst = buf ? rst1 : rst0;

        int nt = tile + GRID;
        int nb = buf ^ 1;
        if (tid < 128 && nt < NUMTILES) stok[nb*128 + tid] = winrow_to_token(nt*128 + tid);
        __syncthreads();
        if (nt < NUMTILES) {
            bf16*  sAn  = nb ? sA1 : sA0;
            float* rstn = nb ? rst1 : rst0;
            const int* st = stok + nb*128;
            const bf16* Ag = A + (size_t)nt*128*96;
            for (int idx = tid; idx < 1536; idx += 512) { int r = idx/12, c = idx%12; cp16(sAn + r*104 + c*8, Ag + r*96 + c*8); }
            for (int idx = tid; idx < 3072; idx += 512) { int r = idx/24, c = idx%24; cp16(rstn + r*96 + c*4, x + (size_t)st[r]*96 + c*4); }
        }
        CPC();

        wmma::fragment<wmma::accumulator, 16, 16, 16, float> acc[3];
        #pragma unroll
        for (int f = 0; f < 3; f++) wmma::fill_fragment(acc[f], 0.f);
        #pragma unroll
        for (int ks = 0; ks < 6; ks++) {
            wmma::fragment<wmma::matrix_a, 16, 16, 16, bf16, wmma::row_major> af;
            wmma::load_matrix_sync(af, sA + (mw*16)*104 + ks*16, 104);
            #pragma unroll
            for (int f = 0; f < 3; f++) {
                wmma::fragment<wmma::matrix_b, 16, 16, 16, bf16, wmma::row_major> bfr;
                wmma::load_matrix_sync(bfr, sW + (ks*16)*104 + nw*48 + f*16, 104);
                wmma::mma_sync(acc[f], af, bfr, acc[f]);
            }
        }
        __syncthreads();
        #pragma unroll
        for (int f = 0; f < 3; f++)
            wmma::store_matrix_sync(stag + (mw*16)*100 + nw*48 + f*16, acc[f], 100, wmma::mem_row_major);
        __syncthreads();

        // epilogue: residual add + LN2 (warp-per-row)
        const int* st = stok + buf*128;
        #pragma unroll
        for (int rr = 0; rr < 8; rr++) {
            int r = warp*8 + rr;
            int tk = st[r];
            float a0 = stag[r*100+lane]    + sbias[lane]    + rst[r*96+lane];
            float a1 = stag[r*100+lane+32] + sbias[lane+32] + rst[r*96+lane+32];
            float a2 = stag[r*100+lane+64] + sbias[lane+64] + rst[r*96+lane+64];
            float mu = wred(a0+a1+a2) * (1.f/96.f);
            float d0 = a0-mu, d1 = a1-mu, d2 = a2-mu;
            float var = wred(d0*d0 + d1*d1 + d2*d2) * (1.f/96.f);
            float rs = rsqrtf(var + 1e-5f);
            size_t o = (size_t)tk * 96;
            y[o+lane]    = a0;  y[o+lane+32] = a1;  y[o+lane+64] = a2;
            hw[o+lane]    = __float2bfloat16(d0*rs*sg[lane]    + sb[lane]);
            hw[o+lane+32] = __float2bfloat16(d1*rs*sg[lane+32] + sb[lane+32]);
            hw[o+lane+64] = __float2bfloat16(d2*rs*sg[lane+64] + sb[lane+64]);
        }
        __syncthreads();
        buf ^= 1;
    }
}

// =====================================================================
// fc1 kernel: GEMM (96 -> 384) + GELU -> bf16
// =====================================================================
__global__ void __launch_bounds__(512, 1)
fc1_kernel(const bf16* __restrict__ A, const float* __restrict__ W1,
           const float* __restrict__ bb, bf16* __restrict__ out)
{
    extern __shared__ __align__(16) char sm[];
    bf16*  sW   = (bf16*)sm;                        // 96*392 = 75264
    bf16*  sA0  = (bf16*)(sm + 75264);              // 26624
    bf16*  sA1  = (bf16*)(sm + 101888);             // 26624
    float* stag = (float*)(sm + 128512);            // 51200
    float* sbias= (float*)(sm + 179712);            // 1536   (total 181248)

    const int tid = threadIdx.x, warp = tid >> 5;
    const int mw = warp >> 1, nw = warp & 1;

    for (int i = tid; i < 96*384; i += 512) { int k = i/384, n = i%384; sW[k*392+n] = __float2bfloat16(W1[i]); }
    for (int i = tid; i < 384; i += 512) sbias[i] = bb[i];

    int tile = blockIdx.x, buf = 0;
    {
        const bf16* Ag = A + (size_t)tile*128*96;
        for (int idx = tid; idx < 1536; idx += 512) { int r = idx/12, c = idx%12; cp16(sA0 + r*104 + c*8, Ag + r*96 + c*8); }
    }
    CPC();
    __syncthreads();

    for (; tile < NUMTILES; tile += GRID) {
        CPW(); __syncthreads();
        bf16* sA = buf ? sA1 : sA0;
        int nt = tile + GRID;
        if (nt < NUMTILES) {
            bf16* sAn = (buf^1) ? sA1 : sA0;
            const bf16* Ag = A + (size_t)nt*128*96;
            for (int idx = tid; idx < 1536; idx += 512) { int r = idx/12, c = idx%12; cp16(sAn + r*104 + c*8, Ag + r*96 + c*8); }
        }
        CPC();

        for (int c = 0; c < 4; c++) {
            wmma::fragment<wmma::accumulator, 16, 16, 16, float> acc[3];
            #pragma unroll
            for (int f = 0; f < 3; f++) wmma::fill_fragment(acc[f], 0.f);
            #pragma unroll
            for (int ks = 0; ks < 6; ks++) {
                wmma::fragment<wmma::matrix_a, 16, 16, 16, bf16, wmma::row_major> af;
                wmma::load_matrix_sync(af, sA + (mw*16)*104 + ks*16, 104);
                #pragma unroll
                for (int f = 0; f < 3; f++) {
                    wmma::fragment<wmma::matrix_b, 16, 16, 16, bf16, wmma::row_major> bfr;
                    wmma::load_matrix_sync(bfr, sW + (ks*16)*392 + c*96 + nw*48 + f*16, 392);
                    wmma::mma_sync(acc[f], af, bfr, acc[f]);
                }
            }
            __syncthreads();
            #pragma unroll
            for (int f = 0; f < 3; f++)
                wmma::store_matrix_sync(stag + (mw*16)*100 + nw*48 + f*16, acc[f], 100, wmma::mem_row_major);
            __syncthreads();
            #pragma unroll
            for (int i2 = tid; i2 < 128*48; i2 += 512) {
                int r = i2/48, p = i2 - r*48;
                float u0 = stag[r*100 + 2*p]     + sbias[c*96 + 2*p];
                float u1 = stag[r*100 + 2*p + 1] + sbias[c*96 + 2*p + 1];
                u0 = 0.5f*u0*(1.f + erff(u0*0.70710678118654752f));
                u1 = 0.5f*u1*(1.f + erff(u1*0.70710678118654752f));
                __nv_bfloat162 pk = __floats2bfloat162_rn(u0, u1);
                *(uint32_t*)(out + ((size_t)(tile*128 + r))*384 + c*96 + 2*p) = *(uint32_t*)&pk;
            }
            __syncthreads();
        }
        buf ^= 1;
    }
}

// =====================================================================
// fc2 kernel: GEMM (384 -> 96) + residual accumulate into y (f32)
// =====================================================================
__global__ void __launch_bounds__(512, 1)
fc2_kernel(const bf16* __restrict__ A, const float* __restrict__ W2,
           const float* __restrict__ bb, float* __restrict__ y)
{
    extern __shared__ __align__(16) char sm[];
    bf16*  sW   = (bf16*)sm;                        // 384*104 = 79872
    bf16*  sA   = (bf16*)(sm + 79872);              // 128*392*2 = 100352
    float* stag = (float*)(sm + 180224);            // 51200
    float* sbias= (float*)(sm + 231424);            // 384    (total 231808)

    const int tid = threadIdx.x, warp = tid >> 5;
    const int mw = warp >> 1, nw = warp & 1;

    for (int i = tid; i < 384*96; i += 512) { int k = i/96, n = i%96; sW[k*104+n] = __float2bfloat16(W2[i]); }
    if (tid < 96) sbias[tid] = bb[tid];
    __syncthreads();

    for (int tile = blockIdx.x; tile < NUMTILES; tile += GRID) {
        const bf16* Ag = A + (size_t)tile*128*384;
        for (int idx = tid; idx < 6144; idx += 512) { int r = idx/48, c = idx%48; cp16(sA + r*392 + c*8, Ag + r*384 + c*8); }
        CPC(); CPW();
        __syncthreads();

        wmma::fragment<wmma::accumulator, 16, 16, 16, float> acc[3];
        #pragma unroll
        for (int f = 0; f < 3; f++) wmma::fill_fragment(acc[f], 0.f);
        #pragma unroll
        for (int ks = 0; ks < 24; ks++) {
            wmma::fragment<wmma::matrix_a, 16, 16, 16, bf16, wmma::row_major> af;
            wmma::load_matrix_sync(af, sA + (mw*16)*392 + ks*16, 392);
            #pragma unroll
            for (int f = 0; f < 3; f++) {
                wmma::fragment<wmma::matrix_b, 16, 16, 16, bf16, wmma::row_major> bfr;
                wmma::load_matrix_sync(bfr, sW + (ks*16)*104 + nw*48 + f*16, 104);
                wmma::mma_sync(acc[f], af, bfr, acc[f]);
            }
        }
        __syncthreads();
        #pragma unroll
        for (int f = 0; f < 3; f++)
            wmma::store_matrix_sync(stag + (mw*16)*100 + nw*48 + f*16, acc[f], 100, wmma::mem_row_major);
        __syncthreads();
        #pragma unroll
        for (int i2 = tid; i2 < 128*96; i2 += 512) {
            int r = i2/96, c = i2 - r*96;
            y[((size_t)(tile*128 + r))*96 + c] += stag[r*100 + c] + sbias[c];
        }
        __syncthreads();
    }
}

// ---------------- window attention (unchanged from R3) ----------------
__global__ void __launch_bounds__(64)
attn_kernel(const bf16* __restrict__ qkv, const float* __restrict__ rpb,
            float* __restrict__ attn_w, bf16* __restrict__ outp) {
    const int blk = blockIdx.x;
    const int h = blk % NHH, w = blk / NHH;
    __shared__ float sq[NN*HD], sk[NN*HD], sv[NN*HD];
    __shared__ float srpb[169];
    __shared__ float s_a[NN*53];
    const int tid = threadIdx.x;

    const bf16* base = qkv + (size_t)w * NN * 288 + h*HD;
    for (int idx = tid; idx < NN*12; idx += 64) {
        int n = idx / 12, p = idx - n*12;
        int which = p >> 2, ch = p & 3;
        uint4 vv = *(const uint4*)(base + (size_t)n*288 + which*96 + ch*8);
        const __nv_bfloat162* b2 = (const __nv_bfloat162*)&vv;
        float* dst = (which == 0 ? sq : which == 1 ? sk : sv) + n*HD + ch*8;
        #pragma unroll
        for (int t = 0; t < 4; t++) { float2 f = __bfloat1622float2(b2[t]); dst[2*t] = f.x; dst[2*t+1] = f.y; }
    }
    for (int idx = tid; idx < 169; idx += 64) srpb[idx] = rpb[idx*NHH + h];
    __syncthreads();

    if (tid < NN) {
        const int n = tid, i1 = n / WSZ, j1 = n % WSZ;
        float q[HD];
        #pragma unroll
        for (int d = 0; d < HD; d++) q[d] = sq[n*HD + d] * SCALEV;
        const float4* sk4 = (const float4*)sk;
        float mx = -1e30f;
        for (int m = 0; m < NN; m++) {
            float s0 = 0.f, s1 = 0.f, s2 = 0.f, s3 = 0.f;
            #pragma unroll
            for (int i = 0; i < 8; i++) {
                float4 kk = sk4[m*8 + i];
                s0 += q[4*i]*kk.x; s1 += q[4*i+1]*kk.y; s2 += q[4*i+2]*kk.z; s3 += q[4*i+3]*kk.w;
            }
            int i2 = m / WSZ, j2 = m % WSZ;
            float dot = (s0 + s1) + (s2 + s3) + srpb[(i1 - i2 + 6)*13 + (j1 - j2 + 6)];
            s_a[n*53 + m] = dot;
            mx = fmaxf(mx, dot);
        }
        float ss = 0.f;
        for (int m = 0; m < NN; m++) { float e = __expf(s_a[n*53 + m] - mx); s_a[n*53 + m] = e; ss += e; }
        float inv = 1.f / ss;
        for (int m = 0; m < NN; m++) s_a[n*53 + m] *= inv;
    }
    __syncthreads();

    if (attn_w) {
        float* ap = attn_w + (size_t)(w*NHH + h) * (NN*NN);
        for (int idx = tid; idx < NN*NN; idx += 64) ap[idx] = s_a[(idx/NN)*53 + idx % NN];
    }

    if (tid < NN) {
        const int n = tid;
        float4 o[8];
        #pragma unroll
        for (int i = 0; i < 8; i++) { o[i].x = 0.f; o[i].y = 0.f; o[i].z = 0.f; o[i].w = 0.f; }
        const float4* sv4 = (const float4*)sv;
        for (int m = 0; m < NN; m++) {
            float a = s_a[n*53 + m];
            #pragma unroll
            for (int i = 0; i < 8; i++) {
                float4 vv = sv4[m*8 + i];
                o[i].x += a*vv.x; o[i].y += a*vv.y; o[i].z += a*vv.z; o[i].w += a*vv.w;
            }
        }
        bf16* op = outp + (size_t)(w*NN + n) * CC + h*HD;
        uint32_t pk[16];
        #pragma unroll
        for (int i = 0; i < 8; i++) {
            __nv_bfloat162 p0 = __floats2bfloat162_rn(o[i].x, o[i].y);
            __nv_bfloat162 p1 = __floats2bfloat162_rn(o[i].z, o[i].w);
            pk[2*i]   = *(uint32_t*)&p0;
            pk[2*i+1] = *(uint32_t*)&p1;
        }
        #pragma unroll
        for (int t = 0; t < 4; t++) ((uint4*)op)[t] = ((const uint4*)pk)[t];
    }
}

// ---------------- launch ----------------
extern "C" void kernel_launch(void* const* d_in, const int* in_sizes, int n_in,
                              void* d_out, int out_size) {
    const float* x      = (const float*)d_in[0];
    const float* w_qkv  = (const float*)d_in[1];
    const float* b_qkv  = (const float*)d_in[2];
    const float* w_proj = (const float*)d_in[3];
    const float* b_proj = (const float*)d_in[4];
    const float* rpb    = (const float*)d_in[5];
    const float* gamma1 = (const float*)d_in[6];
    const float* beta1  = (const float*)d_in[7];
    const float* gamma2 = (const float*)d_in[8];
    const float* beta2  = (const float*)d_in[9];
    const float* w_fc1  = (const float*)d_in[10];
    const float* b_fc1  = (const float*)d_in[11];
    const float* w_fc2  = (const float*)d_in[12];
    const float* b_fc2  = (const float*)d_in[13];

    float* y = (float*)d_out;
    float* attn_w = ((long long)out_size >= YE + AE) ? (y + YE) : (float*)0;

    bf16 *p_hw, *p_qkv, *p_att, *p_hid;
    cudaGetSymbolAddress((void**)&p_hw,  g_hw);
    cudaGetSymbolAddress((void**)&p_qkv, g_qkv);
    cudaGetSymbolAddress((void**)&p_att, g_att);
    cudaGetSymbolAddress((void**)&p_hid, g_hid);

    const int SMQ = 188800, SMP = 224896, SM1 = 181248, SM2 = 231808;
    cudaFuncSetAttribute(qkv_kernel, cudaFuncAttributeMaxDynamicSharedMemorySize, SMQ);
    cudaFuncSetAttribute(proj_kernel, cudaFuncAttributeMaxDynamicSharedMemorySize, SMP);
    cudaFuncSetAttribute(fc1_kernel, cudaFuncAttributeMaxDynamicSharedMemorySize, SM1);
    cudaFuncSetAttribute(fc2_kernel, cudaFuncAttributeMaxDynamicSharedMemorySize, SM2);

    // 1) fused LN1 + gather + qkv GEMM
    qkv_kernel<<<GRID, 512, SMQ>>>(x, w_qkv, b_qkv, gamma1, beta1, p_qkv);
    // 2) window attention (+ attn weights)
    attn_kernel<<<BW*NHH, 64>>>(p_qkv, rpb, attn_w, p_att);
    // 3) proj GEMM + scatter + residual + LN2 -> y, hw
    proj_kernel<<<GRID, 512, SMP>>>(p_att, w_proj, b_proj, x, gamma2, beta2, y, p_hw);
    // 4) fc1 + GELU
    fc1_kernel<<<GRID, 512, SM1>>>(p_hw, w_fc1, b_fc1, p_hid);
    // 5) fc2 + residual into y
    fc2_kernel<<<GRID, 512, SM2>>>(p_hid, w_fc2, b_fc2, y);
}

// round 5
// speedup vs baseline: 4.4345x; 1.3779x over previous
#include <cuda_runtime.h>
#include <cuda_bf16.h>
#include <mma.h>
#include <math.h>
#include <stdint.h>

using namespace nvcuda;
typedef __nv_bfloat16 bf16;

// ---------------- problem constants ----------------
#define Bc     16
#define HDIM   224
#define CC     96
#define LL     (HDIM*HDIM)
#define NTOK   (Bc*LL)              // 802816
#define WSZ    7
#define NN     49
#define NWIN   32
#define BW     (Bc*NWIN*NWIN)       // 16384
#define NHH    3
#define HD     32
#define MLPH   384
#define SHIFTV 3
#define SCALEV 0.17677669529663687f
#define NUMTILES (NTOK/128)         // 6272
#define GRID   148

static const long long YE = (long long)NTOK * CC;
static const long long AE = (long long)BW * NHH * NN * NN;

// ---------------- scratch ----------------
__device__ bf16 g_hw [(size_t)NTOK * CC];
__device__ bf16 g_qkv[(size_t)NTOK * 288];
__device__ bf16 g_att[(size_t)NTOK * CC];
__device__ bf16 g_hid[(size_t)NTOK * MLPH];

// ---------------- helpers ----------------
__device__ __forceinline__ uint32_t smem_u32(const void* p) {
    uint32_t a;
    asm("{ .reg .u64 t; cvta.to.shared.u64 t, %1; cvt.u32.u64 %0, t; }" : "=r"(a) : "l"(p));
    return a;
}
__device__ __forceinline__ void cp16(void* d, const void* s) {
    asm volatile("cp.async.cg.shared.global [%0], [%1], 16;" :: "r"(smem_u32(d)), "l"(s));
}
#define CPC() asm volatile("cp.async.commit_group;" ::: "memory")
#define CPW() asm volatile("cp.async.wait_group 0;" ::: "memory")

__device__ __forceinline__ void ldm_x4(uint32_t& r0, uint32_t& r1, uint32_t& r2, uint32_t& r3, uint32_t addr) {
    asm volatile("ldmatrix.sync.aligned.m8n8.x4.shared.b16 {%0,%1,%2,%3}, [%4];"
                 : "=r"(r0), "=r"(r1), "=r"(r2), "=r"(r3) : "r"(addr));
}
__device__ __forceinline__ void ldm_x4t(uint32_t& r0, uint32_t& r1, uint32_t& r2, uint32_t& r3, uint32_t addr) {
    asm volatile("ldmatrix.sync.aligned.m8n8.x4.trans.shared.b16 {%0,%1,%2,%3}, [%4];"
                 : "=r"(r0), "=r"(r1), "=r"(r2), "=r"(r3) : "r"(addr));
}
__device__ __forceinline__ void mma16816(float* c, uint32_t a0, uint32_t a1, uint32_t a2, uint32_t a3,
                                         uint32_t b0, uint32_t b1) {
    asm volatile("mma.sync.aligned.m16n8k16.row.col.f32.bf16.bf16.f32 "
                 "{%0,%1,%2,%3}, {%4,%5,%6,%7}, {%8,%9}, {%0,%1,%2,%3};"
                 : "+f"(c[0]), "+f"(c[1]), "+f"(c[2]), "+f"(c[3])
                 : "r"(a0), "r"(a1), "r"(a2), "r"(a3), "r"(b0), "r"(b1));
}

__device__ __forceinline__ float wred(float v) {
    #pragma unroll
    for (int o = 16; o; o >>= 1) v += __shfl_xor_sync(0xffffffffu, v, o);
    return v;
}

__device__ __forceinline__ int winrow_to_token(int row) {
    int n  = row % NN;  int w = row / NN;
    int wj = w % NWIN;  int t = w / NWIN;
    int wi = t % NWIN;  int bb = t / NWIN;
    int i = n / WSZ, j = n % WSZ;
    int r = wi*WSZ + i + SHIFTV; if (r >= HDIM) r -= HDIM;
    int c = wj*WSZ + j + SHIFTV; if (c >= HDIM) c -= HDIM;
    return bb*LL + r*HDIM + c;
}

// =====================================================================
// qkv kernel: fused LN1 + shifted-window gather + GEMM (96 -> 288), raw mma
// =====================================================================
__global__ void __launch_bounds__(512, 1)
qkv_kernel(const float* __restrict__ x, const float* __restrict__ Wq,
           const float* __restrict__ bq, const float* __restrict__ g1,
           const float* __restrict__ b1, bf16* __restrict__ out)
{
    extern __shared__ __align__(16) char sm[];
    bf16*  sW   = (bf16*)sm;                       // 96*296*2  = 56832
    bf16*  sA   = (bf16*)(sm + 56832);             // 128*104*2 = 26624
    float* xst0 = (float*)(sm + 83456);            // 49152
    float* xst1 = (float*)(sm + 132608);           // 49152
    int*   stok = (int*)(sm + 181760);             // 1024
    float* sbias= (float*)(sm + 182784);           // 1152
    float* sg   = (float*)(sm + 183936);
    float* sb   = (float*)(sm + 184320);           // total 184704

    const int tid = threadIdx.x, warp = tid >> 5, lane = tid & 31;
    const int mw = warp >> 1, nw = warp & 1;

    for (int i = tid; i < 96*288; i += 512) { int k = i/288, n = i%288; sW[k*296+n] = __float2bfloat16(Wq[i]); }
    for (int i = tid; i < 288; i += 512) sbias[i] = bq[i];
    if (tid < 96) { sg[tid] = g1[tid]; sb[tid] = b1[tid]; }

    const uint32_t aBase = smem_u32(sA) + ((mw*16 + (lane & 15))*104 + (lane >> 4)*8) * 2;
    const uint32_t wBase = smem_u32(sW) + (((lane & 7) + ((lane >> 3) & 1)*8)*296 + (lane >> 4)*8) * 2;

    int tile = blockIdx.x, buf = 0;
    if (tid < 128) stok[tid] = winrow_to_token(tile*128 + tid);
    __syncthreads();
    for (int idx = tid; idx < 3072; idx += 512) {
        int r = idx/24, c = idx%24;
        cp16(xst0 + r*96 + c*4, x + (size_t)stok[r]*96 + c*4);
    }
    CPC();

    for (; tile < NUMTILES; tile += GRID) {
        CPW(); __syncthreads();
        float* xs = buf ? xst1 : xst0;

        // LN1: 16 warps x 8 rows
        #pragma unroll
        for (int rr = 0; rr < 8; rr++) {
            int r = warp*8 + rr;
            float v0 = xs[r*96+lane], v1 = xs[r*96+lane+32], v2 = xs[r*96+lane+64];
            float mu = wred(v0+v1+v2) * (1.f/96.f);
            float d0 = v0-mu, d1 = v1-mu, d2 = v2-mu;
            float var = wred(d0*d0 + d1*d1 + d2*d2) * (1.f/96.f);
            float rs = rsqrtf(var + 1e-5f);
            sA[r*104+lane]    = __float2bfloat16(d0*rs*sg[lane]    + sb[lane]);
            sA[r*104+lane+32] = __float2bfloat16(d1*rs*sg[lane+32] + sb[lane+32]);
            sA[r*104+lane+64] = __float2bfloat16(d2*rs*sg[lane+64] + sb[lane+64]);
        }
        int nt = tile + GRID;
        int nb = buf ^ 1;
        if (tid < 128 && nt < NUMTILES) stok[nb*128 + tid] = winrow_to_token(nt*128 + tid);
        __syncthreads();
        if (nt < NUMTILES) {
            float* xn = nb ? xst1 : xst0;
            const int* st = stok + nb*128;
            for (int idx = tid; idx < 3072; idx += 512) {
                int r = idx/24, c = idx%24;
                cp16(xn + r*96 + c*4, x + (size_t)st[r]*96 + c*4);
            }
        }
        CPC();

        const int r0 = tile*128 + mw*16 + (lane >> 2);
        const int cl = (lane & 3)*2;
        #pragma unroll
        for (int c = 0; c < 3; c++) {
            float acc[6][4];
            #pragma unroll
            for (int f = 0; f < 6; f++) { acc[f][0]=0.f; acc[f][1]=0.f; acc[f][2]=0.f; acc[f][3]=0.f; }
            #pragma unroll
            for (int ks = 0; ks < 6; ks++) {
                uint32_t a0,a1,a2,a3;
                ldm_x4(a0,a1,a2,a3, aBase + ks*32);
                #pragma unroll
                for (int p = 0; p < 3; p++) {
                    uint32_t b0,b1,b2,b3;
                    ldm_x4t(b0,b1,b2,b3, wBase + (ks*16*296 + c*96 + nw*48 + p*16)*2);
                    mma16816(acc[2*p],   a0,a1,a2,a3, b0,b1);
                    mma16816(acc[2*p+1], a0,a1,a2,a3, b2,b3);
                }
            }
            #pragma unroll
            for (int f = 0; f < 6; f++) {
                int col = c*96 + nw*48 + f*8 + cl;
                float bz0 = sbias[col], bz1 = sbias[col+1];
                __nv_bfloat162 p0 = __floats2bfloat162_rn(acc[f][0]+bz0, acc[f][1]+bz1);
                __nv_bfloat162 p1 = __floats2bfloat162_rn(acc[f][2]+bz0, acc[f][3]+bz1);
                *(uint32_t*)(out + (size_t)r0*288 + col)     = *(uint32_t*)&p0;
                *(uint32_t*)(out + (size_t)(r0+8)*288 + col) = *(uint32_t*)&p1;
            }
        }
        buf ^= 1;
    }
}

// =====================================================================
// proj kernel (WMMA + staging, LN2 fused) -- unchanged from R4
// =====================================================================
__global__ void __launch_bounds__(512, 1)
proj_kernel(const bf16* __restrict__ A, const float* __restrict__ Wp,
            const float* __restrict__ bp, const float* __restrict__ x,
            const float* __restrict__ g2, const float* __restrict__ b2,
            float* __restrict__ y, bf16* __restrict__ hw)
{
    extern __shared__ __align__(16) char sm[];
    bf16*  sW   = (bf16*)sm;                        // 19968
    bf16*  sA0  = (bf16*)(sm + 19968);
    bf16*  sA1  = (bf16*)(sm + 46592);
    float* stag = (float*)(sm + 73216);             // 51200
    float* rst0 = (float*)(sm + 124416);
    float* rst1 = (float*)(sm + 173568);
    int*   stok = (int*)(sm + 222720);
    float* sbias= (float*)(sm + 223744);
    float* sg   = (float*)(sm + 224128);
    float* sb   = (float*)(sm + 224512);            // total 224896

    const int tid = threadIdx.x, warp = tid >> 5, lane = tid & 31;
    const int mw = warp >> 1, nw = warp & 1;

    for (int i = tid; i < 96*96; i += 512) { int k = i/96, n = i%96; sW[k*104+n] = __float2bfloat16(Wp[i]); }
    if (tid < 96) { sbias[tid] = bp[tid]; sg[tid] = g2[tid]; sb[tid] = b2[tid]; }

    int tile = blockIdx.x, buf = 0;
    if (tid < 128) stok[tid] = winrow_to_token(tile*128 + tid);
    __syncthreads();
    {
        const bf16* Ag = A + (size_t)tile*128*96;
        for (int idx = tid; idx < 1536; idx += 512) { int r = idx/12, c = idx%12; cp16(sA0 + r*104 + c*8, Ag + r*96 + c*8); }
        for (int idx = tid; idx < 3072; idx += 512) { int r = idx/24, c = idx%24; cp16(rst0 + r*96 + c*4, x + (size_t)stok[r]*96 + c*4); }
    }
    CPC();

    for (; tile < NUMTILES; tile += GRID) {
        CPW(); __syncthreads();
        bf16*  sA  = buf ? sA1 : sA0;
        float* rst = buf ? rst1 : rst0;

        int nt = tile + GRID;
        int nb = buf ^ 1;
        if (tid < 128 && nt < NUMTILES) stok[nb*128 + tid] = winrow_to_token(nt*128 + tid);
        __syncthreads();
        if (nt < NUMTILES) {
            bf16*  sAn  = nb ? sA1 : sA0;
            float* rstn = nb ? rst1 : rst0;
            const int* st = stok + nb*128;
            const bf16* Ag = A + (size_t)nt*128*96;
            for (int idx = tid; idx < 1536; idx += 512) { int r = idx/12, c = idx%12; cp16(sAn + r*104 + c*8, Ag + r*96 + c*8); }
            for (int idx = tid; idx < 3072; idx += 512) { int r = idx/24, c = idx%24; cp16(rstn + r*96 + c*4, x + (size_t)st[r]*96 + c*4); }
        }
        CPC();

        wmma::fragment<wmma::accumulator, 16, 16, 16, float> acc[3];
        #pragma unroll
        for (int f = 0; f < 3; f++) wmma::fill_fragment(acc[f], 0.f);
        #pragma unroll
        for (int ks = 0; ks < 6; ks++) {
            wmma::fragment<wmma::matrix_a, 16, 16, 16, bf16, wmma::row_major> af;
            wmma::load_matrix_sync(af, sA + (mw*16)*104 + ks*16, 104);
            #pragma unroll
            for (int f = 0; f < 3; f++) {
                wmma::fragment<wmma::matrix_b, 16, 16, 16, bf16, wmma::row_major> bfr;
                wmma::load_matrix_sync(bfr, sW + (ks*16)*104 + nw*48 + f*16, 104);
                wmma::mma_sync(acc[f], af, bfr, acc[f]);
            }
        }
        __syncthreads();
        #pragma unroll
        for (int f = 0; f < 3; f++)
            wmma::store_matrix_sync(stag + (mw*16)*100 + nw*48 + f*16, acc[f], 100, wmma::mem_row_major);
        __syncthreads();

        const int* st = stok + buf*128;
        #pragma unroll
        for (int rr = 0; rr < 8; rr++) {
            int r = warp*8 + rr;
            int tk = st[r];
            float a0 = stag[r*100+lane]    + sbias[lane]    + rst[r*96+lane];
            float a1 = stag[r*100+lane+32] + sbias[lane+32] + rst[r*96+lane+32];
            float a2 = stag[r*100+lane+64] + sbias[lane+64] + rst[r*96+lane+64];
            float mu = wred(a0+a1+a2) * (1.f/96.f);
            float d0 = a0-mu, d1 = a1-mu, d2 = a2-mu;
            float var = wred(d0*d0 + d1*d1 + d2*d2) * (1.f/96.f);
            float rs = rsqrtf(var + 1e-5f);
            size_t o = (size_t)tk * 96;
            y[o+lane]    = a0;  y[o+lane+32] = a1;  y[o+lane+64] = a2;
            hw[o+lane]    = __float2bfloat16(d0*rs*sg[lane]    + sb[lane]);
            hw[o+lane+32] = __float2bfloat16(d1*rs*sg[lane+32] + sb[lane+32]);
            hw[o+lane+64] = __float2bfloat16(d2*rs*sg[lane+64] + sb[lane+64]);
        }
        __syncthreads();
        buf ^= 1;
    }
}

// =====================================================================
// fc1 kernel: GEMM (96 -> 384) + GELU -> bf16, raw mma, direct store
// =====================================================================
__global__ void __launch_bounds__(512, 1)
fc1_kernel(const bf16* __restrict__ A, const float* __restrict__ W1,
           const float* __restrict__ bb, bf16* __restrict__ out)
{
    extern __shared__ __align__(16) char sm[];
    bf16*  sW   = (bf16*)sm;                        // 96*392*2 = 75264
    bf16*  sA0  = (bf16*)(sm + 75264);              // 26624
    bf16*  sA1  = (bf16*)(sm + 101888);             // 26624
    float* sbias= (float*)(sm + 128512);            // 1536 (total 130048)

    const int tid = threadIdx.x, warp = tid >> 5, lane = tid & 31;
    const int mw = warp >> 1, nw = warp & 1;

    for (int i = tid; i < 96*384; i += 512) { int k = i/384, n = i%384; sW[k*392+n] = __float2bfloat16(W1[i]); }
    for (int i = tid; i < 384; i += 512) sbias[i] = bb[i];

    const uint32_t wBase = smem_u32(sW) + (((lane & 7) + ((lane >> 3) & 1)*8)*392 + (lane >> 4)*8) * 2;
    const uint32_t aOff  = ((mw*16 + (lane & 15))*104 + (lane >> 4)*8) * 2;

    int tile = blockIdx.x, buf = 0;
    {
        const bf16* Ag = A + (size_t)tile*128*96;
        for (int idx = tid; idx < 1536; idx += 512) { int r = idx/12, c = idx%12; cp16(sA0 + r*104 + c*8, Ag + r*96 + c*8); }
    }
    CPC();

    for (; tile < NUMTILES; tile += GRID) {
        CPW(); __syncthreads();
        uint32_t aBase = smem_u32(buf ? sA1 : sA0) + aOff;
        int nt = tile + GRID;
        if (nt < NUMTILES) {
            bf16* sAn = (buf^1) ? sA1 : sA0;
            const bf16* Ag = A + (size_t)nt*128*96;
            for (int idx = tid; idx < 1536; idx += 512) { int r = idx/12, c = idx%12; cp16(sAn + r*104 + c*8, Ag + r*96 + c*8); }
        }
        CPC();

        const int r0 = tile*128 + mw*16 + (lane >> 2);
        const int cl = (lane & 3)*2;
        #pragma unroll
        for (int c = 0; c < 4; c++) {
            float acc[6][4];
            #pragma unroll
            for (int f = 0; f < 6; f++) { acc[f][0]=0.f; acc[f][1]=0.f; acc[f][2]=0.f; acc[f][3]=0.f; }
            #pragma unroll
            for (int ks = 0; ks < 6; ks++) {
                uint32_t a0,a1,a2,a3;
                ldm_x4(a0,a1,a2,a3, aBase + ks*32);
                #pragma unroll
                for (int p = 0; p < 3; p++) {
                    uint32_t b0,b1,b2,b3;
                    ldm_x4t(b0,b1,b2,b3, wBase + (ks*16*392 + c*96 + nw*48 + p*16)*2);
                    mma16816(acc[2*p],   a0,a1,a2,a3, b0,b1);
                    mma16816(acc[2*p+1], a0,a1,a2,a3, b2,b3);
                }
            }
            #pragma unroll
            for (int f = 0; f < 6; f++) {
                int col = c*96 + nw*48 + f*8 + cl;
                float u0 = acc[f][0] + sbias[col];
                float u1 = acc[f][1] + sbias[col+1];
                float u2 = acc[f][2] + sbias[col];
                float u3 = acc[f][3] + sbias[col+1];
                u0 = 0.5f*u0*(1.f + erff(u0*0.70710678118654752f));
                u1 = 0.5f*u1*(1.f + erff(u1*0.70710678118654752f));
                u2 = 0.5f*u2*(1.f + erff(u2*0.70710678118654752f));
                u3 = 0.5f*u3*(1.f + erff(u3*0.70710678118654752f));
                __nv_bfloat162 p0 = __floats2bfloat162_rn(u0, u1);
                __nv_bfloat162 p1 = __floats2bfloat162_rn(u2, u3);
                *(uint32_t*)(out + (size_t)r0*384 + col)     = *(uint32_t*)&p0;
                *(uint32_t*)(out + (size_t)(r0+8)*384 + col) = *(uint32_t*)&p1;
            }
        }
        buf ^= 1;
    }
}

// =====================================================================
// fc2 kernel: GEMM (384 -> 96) + residual += into y, raw mma,
// K streamed in 4 double-buffered chunks of 96
// =====================================================================
__global__ void __launch_bounds__(512, 1)
fc2_kernel(const bf16* __restrict__ A, const float* __restrict__ W2,
           const float* __restrict__ bb, float* __restrict__ y)
{
    extern __shared__ __align__(16) char sm[];
    bf16*  sW   = (bf16*)sm;                        // 384*104*2 = 79872
    bf16*  sA0  = (bf16*)(sm + 79872);              // 26624
    bf16*  sA1  = (bf16*)(sm + 106496);             // 26624
    float* sbias= (float*)(sm + 133120);            // 384 (total 133504)

    const int tid = threadIdx.x, warp = tid >> 5, lane = tid & 31;
    const int mw = warp >> 1, nw = warp & 1;

    for (int i = tid; i < 384*96; i += 512) { int k = i/96, n = i%96; sW[k*104+n] = __float2bfloat16(W2[i]); }
    if (tid < 96) sbias[tid] = bb[tid];

    const uint32_t wBase = smem_u32(sW) + (((lane & 7) + ((lane >> 3) & 1)*8)*104 + (lane >> 4)*8) * 2;
    const uint32_t aOff  = ((mw*16 + (lane & 15))*104 + (lane >> 4)*8) * 2;
    const uint32_t sA0u = smem_u32(sA0), sA1u = smem_u32(sA1);

    int tile = blockIdx.x;
    {   // prefetch tile0 chunk0
        const bf16* Ag = A + (size_t)tile*128*384;
        for (int idx = tid; idx < 1536; idx += 512) { int r = idx/12, c = idx%12; cp16(sA0 + r*104 + c*8, Ag + r*384 + c*8); }
    }
    CPC();
    __syncthreads();

    for (; tile < NUMTILES; tile += GRID) {
        float acc[6][4];
        #pragma unroll
        for (int f = 0; f < 6; f++) { acc[f][0]=0.f; acc[f][1]=0.f; acc[f][2]=0.f; acc[f][3]=0.f; }

        #pragma unroll
        for (int kc = 0; kc < 4; kc++) {
            CPW(); __syncthreads();
            // prefetch next chunk (or next tile chunk 0)
            int ntile = (kc < 3) ? tile : tile + GRID;
            int nkc   = (kc < 3) ? kc + 1 : 0;
            if (ntile < NUMTILES) {
                bf16* sAn = ((kc+1) & 1) ? sA1 : sA0;
                const bf16* Ag = A + (size_t)ntile*128*384 + nkc*96;
                for (int idx = tid; idx < 1536; idx += 512) { int r = idx/12, c = idx%12; cp16(sAn + r*104 + c*8, Ag + r*384 + c*8); }
            }
            CPC();

            uint32_t aBase = ((kc & 1) ? sA1u : sA0u) + aOff;
            #pragma unroll
            for (int ks = 0; ks < 6; ks++) {
                uint32_t a0,a1,a2,a3;
                ldm_x4(a0,a1,a2,a3, aBase + ks*32);
                #pragma unroll
                for (int p = 0; p < 3; p++) {
                    uint32_t b0,b1,b2,b3;
                    ldm_x4t(b0,b1,b2,b3, wBase + ((kc*96 + ks*16)*104 + nw*48 + p*16)*2);
                    mma16816(acc[2*p],   a0,a1,a2,a3, b0,b1);
                    mma16816(acc[2*p+1], a0,a1,a2,a3, b2,b3);
                }
            }
        }

        const int r0 = tile*128 + mw*16 + (lane >> 2);
        const int cl = (lane & 3)*2;
        #pragma unroll
        for (int f = 0; f < 6; f++) {
            int col = nw*48 + f*8 + cl;
            float bz0 = sbias[col], bz1 = sbias[col+1];
            float2* p0 = (float2*)(y + (size_t)r0*96 + col);
            float2* p1 = (float2*)(y + (size_t)(r0+8)*96 + col);
            float2 v0 = *p0, v1 = *p1;
            v0.x += acc[f][0] + bz0;  v0.y += acc[f][1] + bz1;
            v1.x += acc[f][2] + bz0;  v1.y += acc[f][3] + bz1;
            *p0 = v0;  *p1 = v1;
        }
    }
}

// ---------------- window attention (sq dropped -> +occupancy) ----------------
__global__ void __launch_bounds__(64)
attn_kernel(const bf16* __restrict__ qkv, const float* __restrict__ rpb,
            float* __restrict__ attn_w, bf16* __restrict__ outp) {
    const int blk = blockIdx.x;
    const int h = blk % NHH, w = blk / NHH;
    __shared__ float sk[NN*HD], sv[NN*HD];
    __shared__ float srpb[169];
    __shared__ float s_a[NN*53];
    const int tid = threadIdx.x;

    const bf16* base = qkv + (size_t)w * NN * 288 + h*HD;
    for (int idx = tid; idx < NN*8; idx += 64) {
        int n = idx >> 3, p = idx & 7;
        int which = p >> 2, ch = p & 3;           // which: 0=k,1=v
        uint4 vv = *(const uint4*)(base + (size_t)n*288 + 96 + which*96 + ch*8);
        const __nv_bfloat162* b2 = (const __nv_bfloat162*)&vv;
        float* dst = (which == 0 ? sk : sv) + n*HD + ch*8;
        #pragma unroll
        for (int t = 0; t < 4; t++) { float2 f = __bfloat1622float2(b2[t]); dst[2*t] = f.x; dst[2*t+1] = f.y; }
    }
    for (int idx = tid; idx < 169; idx += 64) srpb[idx] = rpb[idx*NHH + h];
    __syncthreads();

    if (tid < NN) {
        const int n = tid, i1 = n / WSZ, j1 = n % WSZ;
        float q[HD];
        const bf16* qp = base + (size_t)n*288;
        #pragma unroll
        for (int t = 0; t < 4; t++) {
            uint4 vv = ((const uint4*)qp)[t];
            const __nv_bfloat162* b2 = (const __nv_bfloat162*)&vv;
            #pragma unroll
            for (int u = 0; u < 4; u++) {
                float2 f = __bfloat1622float2(b2[u]);
                q[t*8 + 2*u]     = f.x * SCALEV;
                q[t*8 + 2*u + 1] = f.y * SCALEV;
            }
        }
        const float4* sk4 = (const float4*)sk;
        float mx = -1e30f;
        for (int m = 0; m < NN; m++) {
            float s0 = 0.f, s1 = 0.f, s2 = 0.f, s3 = 0.f;
            #pragma unroll
            for (int i = 0; i < 8; i++) {
                float4 kk = sk4[m*8 + i];
                s0 += q[4*i]*kk.x; s1 += q[4*i+1]*kk.y; s2 += q[4*i+2]*kk.z; s3 += q[4*i+3]*kk.w;
            }
            int i2 = m / WSZ, j2 = m % WSZ;
            float dot = (s0 + s1) + (s2 + s3) + srpb[(i1 - i2 + 6)*13 + (j1 - j2 + 6)];
            s_a[n*53 + m] = dot;
            mx = fmaxf(mx, dot);
        }
        float ss = 0.f;
        for (int m = 0; m < NN; m++) { float e = __expf(s_a[n*53 + m] - mx); s_a[n*53 + m] = e; ss += e; }
        float inv = 1.f / ss;
        for (int m = 0; m < NN; m++) s_a[n*53 + m] *= inv;
    }
    __syncthreads();

    if (attn_w) {
        float* ap = attn_w + (size_t)(w*NHH + h) * (NN*NN);
        for (int idx = tid; idx < NN*NN; idx += 64) ap[idx] = s_a[(idx/NN)*53 + idx % NN];
    }

    if (tid < NN) {
        const int n = tid;
        float4 o[8];
        #pragma unroll
        for (int i = 0; i < 8; i++) { o[i].x = 0.f; o[i].y = 0.f; o[i].z = 0.f; o[i].w = 0.f; }
        const float4* sv4 = (const float4*)sv;
        for (int m = 0; m < NN; m++) {
            float a = s_a[n*53 + m];
            #pragma unroll
            for (int i = 0; i < 8; i++) {
                float4 vv = sv4[m*8 + i];
                o[i].x += a*vv.x; o[i].y += a*vv.y; o[i].z += a*vv.z; o[i].w += a*vv.w;
            }
        }
        bf16* op = outp + (size_t)(w*NN + n) * CC + h*HD;
        uint32_t pk[16];
        #pragma unroll
        for (int i = 0; i < 8; i++) {
            __nv_bfloat162 p0 = __floats2bfloat162_rn(o[i].x, o[i].y);
            __nv_bfloat162 p1 = __floats2bfloat162_rn(o[i].z, o[i].w);
            pk[2*i]   = *(uint32_t*)&p0;
            pk[2*i+1] = *(uint32_t*)&p1;
        }
        #pragma unroll
        for (int t = 0; t < 4; t++) ((uint4*)op)[t] = ((const uint4*)pk)[t];
    }
}

// ---------------- launch ----------------
extern "C" void kernel_launch(void* const* d_in, const int* in_sizes, int n_in,
                              void* d_out, int out_size) {
    const float* x      = (const float*)d_in[0];
    const float* w_qkv  = (const float*)d_in[1];
    const float* b_qkv  = (const float*)d_in[2];
    const float* w_proj = (const float*)d_in[3];
    const float* b_proj = (const float*)d_in[4];
    const float* rpb    = (const float*)d_in[5];
    const float* gamma1 = (const float*)d_in[6];
    const float* beta1  = (const float*)d_in[7];
    const float* gamma2 = (const float*)d_in[8];
    const float* beta2  = (const float*)d_in[9];
    const float* w_fc1  = (const float*)d_in[10];
    const float* b_fc1  = (const float*)d_in[11];
    const float* w_fc2  = (const float*)d_in[12];
    const float* b_fc2  = (const float*)d_in[13];

    float* y = (float*)d_out;
    float* attn_w = ((long long)out_size >= YE + AE) ? (y + YE) : (float*)0;

    bf16 *p_hw, *p_qkv, *p_att, *p_hid;
    cudaGetSymbolAddress((void**)&p_hw,  g_hw);
    cudaGetSymbolAddress((void**)&p_qkv, g_qkv);
    cudaGetSymbolAddress((void**)&p_att, g_att);
    cudaGetSymbolAddress((void**)&p_hid, g_hid);

    const int SMQ = 184704, SMP = 224896, SM1 = 130048, SM2 = 133504;
    cudaFuncSetAttribute(qkv_kernel, cudaFuncAttributeMaxDynamicSharedMemorySize, SMQ);
    cudaFuncSetAttribute(proj_kernel, cudaFuncAttributeMaxDynamicSharedMemorySize, SMP);
    cudaFuncSetAttribute(fc1_kernel, cudaFuncAttributeMaxDynamicSharedMemorySize, SM1);
    cudaFuncSetAttribute(fc2_kernel, cudaFuncAttributeMaxDynamicSharedMemorySize, SM2);

    // 1) fused LN1 + gather + qkv GEMM
    qkv_kernel<<<GRID, 512, SMQ>>>(x, w_qkv, b_qkv, gamma1, beta1, p_qkv);
    // 2) window attention (+ attn weights)
    attn_kernel<<<BW*NHH, 64>>>(p_qkv, rpb, attn_w, p_att);
    // 3) proj GEMM + scatter + residual + LN2 -> y, hw
    proj_kernel<<<GRID, 512, SMP>>>(p_att, w_proj, b_proj, x, gamma2, beta2, y, p_hw);
    // 4) fc1 + GELU
    fc1_kernel<<<GRID, 512, SM1>>>(p_hw, w_fc1, b_fc1, p_hid);
    // 5) fc2 + residual into y
    fc2_kernel<<<GRID, 512, SM2>>>(p_hid, w_fc2, b_fc2, y);
}